// round 4
// baseline (speedup 1.0000x reference)
#include <cuda_runtime.h>
#include <cuda_bf16.h>

#define B_   16
#define A_   262144
#define G_   128
#define NTHR 256
#define NBLK (A_ / NTHR)      /* 1024 */
#define NWARP (NTHR / 32)     /* 8 */

// Per-(batch, block) partials. Written fresh every launch -> no zeroing needed,
// fully deterministic (no floating-point atomics anywhere).
__device__ float g_psum[B_ * NBLK];
__device__ int   g_pcnt[B_ * NBLK];

__global__ void __launch_bounds__(NTHR)
retina_loss_main(const float4* __restrict__ bbox,     // [B, A, 4]
                 const float4* __restrict__ anchors,  // [A, 4]
                 const float4* __restrict__ gt,       // [B, G, 4]
                 const int*    __restrict__ midx)     // [B, A]
{
    __shared__ float s_sum[B_ * NWARP];
    __shared__ int   s_cnt[B_ * NWARP];

    const int tid  = threadIdx.x;
    const int lane = tid & 31;
    const int warp = tid >> 5;
    const int a    = blockIdx.x * NTHR + tid;   // NBLK*NTHR == A_, no guard needed

    // Anchor loaded ONCE, reused for all 16 batches.
    float4 an = anchors[a];
    float ex_w  = an.z - an.x;
    float ex_h  = an.w - an.y;
    float ex_cx = an.x + 0.5f * ex_w;
    float ex_cy = an.y + 0.5f * ex_h;
    float iw = 1.0f / ex_w;
    float ih = 1.0f / ex_h;

    // Front-batch all 16 matched-index loads (MLP).
    int m[B_];
#pragma unroll
    for (int b = 0; b < B_; b++)
        m[b] = midx[(size_t)b * A_ + a];

#pragma unroll
    for (int b = 0; b < B_; b++) {
        const bool fg = (m[b] >= 0);
        // Unconditional load: 98.5% of anchors are foreground; predicating
        // would serialize and save almost no traffic.
        float4 r = bbox[(size_t)b * A_ + a];
        float4 g = gt[b * G_ + (fg ? m[b] : 0)];   // 32 KB total, L1-resident

        float gw  = g.z - g.x;
        float gh  = g.w - g.y;
        float gcx = g.x + 0.5f * gw;
        float gcy = g.y + 0.5f * gh;

        float dx = (gcx - ex_cx) * iw;
        float dy = (gcy - ex_cy) * ih;
        float dw = __logf(gw * iw);   // MUFU path; abs err ~1e-6, well under 1e-3
        float dh = __logf(gh * ih);

        float l1 = fabsf(r.x - dx) + fabsf(r.y - dy)
                 + fabsf(r.z - dw) + fabsf(r.w - dh);
        l1 = fg ? l1 : 0.0f;

        // Warp reduce: sum via shfl, count via ballot+popc (1 instr).
#pragma unroll
        for (int o = 16; o > 0; o >>= 1)
            l1 += __shfl_down_sync(0xffffffffu, l1, o);
        unsigned bal = __ballot_sync(0xffffffffu, fg);

        if (lane == 0) {
            s_sum[b * NWARP + warp] = l1;
            s_cnt[b * NWARP + warp] = __popc(bal);
        }
    }
    __syncthreads();

    // Deterministic block combine: thread t (<16) owns batch t, folds 8 warp
    // partials serially, writes the per-(batch, block) partial.
    if (tid < B_) {
        float s = 0.0f;
        int   c = 0;
#pragma unroll
        for (int w = 0; w < NWARP; w++) {
            s += s_sum[tid * NWARP + w];
            c += s_cnt[tid * NWARP + w];
        }
        g_psum[tid * NBLK + blockIdx.x] = s;
        g_pcnt[tid * NBLK + blockIdx.x] = c;
    }
}

__global__ void __launch_bounds__(NBLK)
retina_loss_final(float* __restrict__ out)
{
    __shared__ float rs[NBLK];
    __shared__ int   rc[NBLK];
    __shared__ float per_image[B_];

    const int t = threadIdx.x;

#pragma unroll 1
    for (int b = 0; b < B_; b++) {
        rs[t] = g_psum[b * NBLK + t];
        rc[t] = g_pcnt[b * NBLK + t];
        __syncthreads();
#pragma unroll
        for (int s = NBLK / 2; s > 0; s >>= 1) {
            if (t < s) { rs[t] += rs[t + s]; rc[t] += rc[t + s]; }
            __syncthreads();
        }
        if (t == 0) {
            int c = rc[0];
            per_image[b] = rs[0] / (float)(c > 1 ? c : 1);
        }
        __syncthreads();
    }

    if (t == 0) {
        float tot = 0.0f;
#pragma unroll
        for (int b = 0; b < B_; b++) tot += per_image[b];
        *out = tot / (float)B_;
    }
}

extern "C" void kernel_launch(void* const* d_in, const int* in_sizes, int n_in,
                              void* d_out, int out_size)
{
    const float4* bbox    = (const float4*)d_in[0];  // bbox_regression [B, A, 4] f32
    const float4* anchors = (const float4*)d_in[1];  // anchors [A, 4] f32
    const float4* gt      = (const float4*)d_in[2];  // gt_boxes [B, G, 4] f32
    const int*    midx    = (const int*)d_in[3];     // matched_idxs [B, A] i32

    retina_loss_main<<<NBLK, NTHR>>>(bbox, anchors, gt, midx);
    retina_loss_final<<<1, NBLK>>>((float*)d_out);
}

// round 5
// speedup vs baseline: 1.7219x; 1.7219x over previous
#include <cuda_runtime.h>
#include <cuda_bf16.h>

#define B_    16
#define A_    262144
#define G_    128
#define NTHR  256
#define NBLK  (A_ / NTHR)      /* 1024 */
#define NWARP (NTHR / 32)      /* 8 */

// Per-(batch, block) partials. Written fresh every launch -> no zeroing needed,
// fully deterministic (no floating-point atomics anywhere).
__device__ float g_psum[B_ * NBLK];
__device__ int   g_pcnt[B_ * NBLK];
__device__ unsigned g_done = 0;   // reset by the last block each launch

__global__ void __launch_bounds__(NTHR)
retina_loss_fused(const float4* __restrict__ bbox,     // [B, A, 4]
                  const float4* __restrict__ anchors,  // [A, 4]
                  const float4* __restrict__ gt,       // [B, G, 4]
                  const int*    __restrict__ midx,     // [B, A]
                  float*        __restrict__ out)
{
    __shared__ float s_sum[B_ * NWARP];
    __shared__ int   s_cnt[B_ * NWARP];
    __shared__ float s_img[B_];
    __shared__ unsigned s_ticket;

    const int tid  = threadIdx.x;
    const int lane = tid & 31;
    const int warp = tid >> 5;
    const int a    = blockIdx.x * NTHR + tid;   // NBLK*NTHR == A_, no guard needed

    // Anchor loaded ONCE, reused for all 16 batches.
    float4 an = anchors[a];
    float ex_w  = an.z - an.x;
    float ex_h  = an.w - an.y;
    float ex_cx = an.x + 0.5f * ex_w;
    float ex_cy = an.y + 0.5f * ex_h;
    float iw = 1.0f / ex_w;
    float ih = 1.0f / ex_h;

    // Front-batch all 16 matched-index loads (MLP).
    int m[B_];
#pragma unroll
    for (int b = 0; b < B_; b++)
        m[b] = midx[(size_t)b * A_ + a];

#pragma unroll
    for (int b = 0; b < B_; b++) {
        const bool fg = (m[b] >= 0);
        // Unconditional load: vast majority of anchors are foreground;
        // predicating would save almost no traffic.
        float4 r = bbox[(size_t)b * A_ + a];
        float4 g = gt[b * G_ + (fg ? m[b] : 0)];   // 32 KB total, L1/L2-resident

        float gw  = g.z - g.x;
        float gh  = g.w - g.y;
        float gcx = g.x + 0.5f * gw;
        float gcy = g.y + 0.5f * gh;

        float dx = (gcx - ex_cx) * iw;
        float dy = (gcy - ex_cy) * ih;
        float dw = __logf(gw * iw);   // MUFU path; abs err ~1e-6, well under 1e-3
        float dh = __logf(gh * ih);

        float l1 = fabsf(r.x - dx) + fabsf(r.y - dy)
                 + fabsf(r.z - dw) + fabsf(r.w - dh);
        l1 = fg ? l1 : 0.0f;

        // Warp reduce: sum via shfl, count via ballot+popc (1 instr).
#pragma unroll
        for (int o = 16; o > 0; o >>= 1)
            l1 += __shfl_down_sync(0xffffffffu, l1, o);
        unsigned bal = __ballot_sync(0xffffffffu, fg);

        if (lane == 0) {
            s_sum[b * NWARP + warp] = l1;
            s_cnt[b * NWARP + warp] = __popc(bal);
        }
    }
    __syncthreads();

    // Deterministic block combine: thread t (<16) owns batch t, folds 8 warp
    // partials serially, writes the per-(batch, block) partial.
    if (tid < B_) {
        float s = 0.0f;
        int   c = 0;
#pragma unroll
        for (int w = 0; w < NWARP; w++) {
            s += s_sum[tid * NWARP + w];
            c += s_cnt[tid * NWARP + w];
        }
        g_psum[tid * NBLK + blockIdx.x] = s;
        g_pcnt[tid * NBLK + blockIdx.x] = c;
    }

    // ---- last-block-done final reduction (replaces the second kernel) ----
    __threadfence();              // make this block's partials L2-visible
    __syncthreads();
    if (tid == 0)
        s_ticket = atomicAdd(&g_done, 1u);
    __syncthreads();

    if (s_ticket == (unsigned)(NBLK - 1)) {
        // This block is last: all partials are in L2. Warp-per-batch reduce,
        // fixed iteration order -> bit-deterministic result.
        for (int b = warp; b < B_; b += NWARP) {
            float s = 0.0f;
            int   c = 0;
#pragma unroll 8
            for (int i = lane; i < NBLK; i += 32) {
                s += __ldcg(&g_psum[b * NBLK + i]);
                c += __ldcg(&g_pcnt[b * NBLK + i]);
            }
#pragma unroll
            for (int o = 16; o > 0; o >>= 1) {
                s += __shfl_down_sync(0xffffffffu, s, o);
                c += __shfl_down_sync(0xffffffffu, c, o);
            }
            if (lane == 0)
                s_img[b] = s / (float)(c > 1 ? c : 1);
        }
        __syncthreads();
        if (tid == 0) {
            float tot = 0.0f;
#pragma unroll
            for (int b = 0; b < B_; b++) tot += s_img[b];
            *out = tot * (1.0f / (float)B_);
            g_done = 0;           // reset for the next (graph-replayed) launch
        }
    }
}

extern "C" void kernel_launch(void* const* d_in, const int* in_sizes, int n_in,
                              void* d_out, int out_size)
{
    const float4* bbox    = (const float4*)d_in[0];  // bbox_regression [B, A, 4] f32
    const float4* anchors = (const float4*)d_in[1];  // anchors [A, 4] f32
    const float4* gt      = (const float4*)d_in[2];  // gt_boxes [B, G, 4] f32
    const int*    midx    = (const int*)d_in[3];     // matched_idxs [B, A] i32

    retina_loss_fused<<<NBLK, NTHR>>>(bbox, anchors, gt, midx, (float*)d_out);
}